// round 16
// baseline (speedup 1.0000x reference)
#include <cuda_runtime.h>
#include <stdio.h>
#include <stdlib.h>
#include <string.h>
#include <math.h>

#define T_LEN   2048
#define B_SZ    2
#define D_MODEL 1024
#define D_INNER 2048
#define D_STATE 16
#define NTOK    (B_SZ * T_LEN)   // 4096
#define NPROJ   33               // 1 + 2*D_STATE

// ---------------- scratch (device globals; no allocation allowed) ----------
__device__ float g_xn[(size_t)NTOK * D_MODEL];
__device__ float g_xz[(size_t)NTOK * 2 * D_INNER];
__device__ float g_xc[(size_t)NTOK * D_INNER];
__device__ float g_ssm[(size_t)NTOK * NPROJ];
__device__ float g_yf[(size_t)NTOK * D_INNER];
__device__ float g_out[(size_t)NTOK * D_MODEL];   // staging for final output
__device__ double g_acc[8];
__device__ int    g_max[8];
__device__ double g_diag[64];

static inline float host_bits_to_float(int b) {
    float f;
    memcpy(&f, &b, sizeof(f));
    return f;
}

// ---------------- diagnostics kernels (correctness call only) --------------
__global__ void k_stat(const float* __restrict__ p, long long n, int slot) {
    long long stride = (long long)gridDim.x * blockDim.x;
    double s = 0.0;
    float mx = 0.f;
    for (long long i = blockIdx.x * (long long)blockDim.x + threadIdx.x;
         i < n; i += stride) {
        float v = fabsf(p[i]);
        s += v;
        mx = fmaxf(mx, v);
    }
    for (int o = 16; o; o >>= 1) {
        s += __shfl_xor_sync(~0u, s, o);
        mx = fmaxf(mx, __shfl_xor_sync(~0u, mx, o));
    }
    if ((threadIdx.x & 31) == 0) {
        atomicAdd(&g_acc[slot], s);
        atomicMax(&g_max[slot], __float_as_int(mx));
    }
}

__global__ void k_argmax(const float* __restrict__ p, long long n) {
    __shared__ float vmax[256];
    __shared__ long long imax[256];
    float mv = -1.f;
    long long mi = 0;
    for (long long i = threadIdx.x; i < n; i += 256) {
        float v = fabsf(p[i]);
        if (v > mv) { mv = v; mi = i; }
    }
    vmax[threadIdx.x] = mv;
    imax[threadIdx.x] = mi;
    __syncthreads();
    for (int s = 128; s; s >>= 1) {
        if (threadIdx.x < s && vmax[threadIdx.x + s] > vmax[threadIdx.x]) {
            vmax[threadIdx.x] = vmax[threadIdx.x + s];
            imax[threadIdx.x] = imax[threadIdx.x + s];
        }
        __syncthreads();
    }
    if (threadIdx.x == 0) {
        g_diag[32] = vmax[0];
        g_diag[33] = (double)imax[0];
    }
}

// golden recompute: GEMM2 at argmax + 2 fixed spots; GEMM1 at 1 spot
__global__ void k_gold(const float* __restrict__ yf,
                       const float* __restrict__ W_out,
                       const float* __restrict__ x,
                       const float* __restrict__ stage,
                       const float* __restrict__ xn,
                       const float* __restrict__ W_in,
                       const float* __restrict__ xz) {
    if (threadIdx.x != 0 || blockIdx.x != 0) return;
    long long idx = (long long)g_diag[33];
    int row = (int)(idx / D_MODEL);
    int col = (int)(idx % D_MODEL);
    g_diag[34] = row;
    g_diag[35] = col;

    double so = x[(size_t)row * D_MODEL + col];
    for (int k = 0; k < D_INNER; k++)
        so += (double)yf[(size_t)row * D_INNER + k] *
              (double)W_out[(size_t)k * D_MODEL + col];
    g_diag[0] = so;
    g_diag[1] = stage[idx];

    double s2 = x[(size_t)100 * D_MODEL + 100];
    for (int k = 0; k < D_INNER; k++)
        s2 += (double)yf[(size_t)100 * D_INNER + k] *
              (double)W_out[(size_t)k * D_MODEL + 100];
    g_diag[2] = s2;
    g_diag[3] = stage[(size_t)100 * D_MODEL + 100];

    double s3 = x[(size_t)3000 * D_MODEL + 500];
    for (int k = 0; k < D_INNER; k++)
        s3 += (double)yf[(size_t)3000 * D_INNER + k] *
              (double)W_out[(size_t)k * D_MODEL + 500];
    g_diag[4] = s3;
    g_diag[5] = stage[(size_t)3000 * D_MODEL + 500];

    // GEMM1 spot-check: xz[1000, 3000]
    double s1 = 0.0;
    for (int k = 0; k < D_MODEL; k++)
        s1 += (double)xn[(size_t)1000 * D_MODEL + k] *
              (double)W_in[(size_t)k * (2 * D_INNER) + 3000];
    g_diag[6] = s1;
    g_diag[7] = xz[(size_t)1000 * (2 * D_INNER) + 3000];
}

__global__ void k_readback(const float* __restrict__ dout) {
    if (threadIdx.x != 0 || blockIdx.x != 0) return;
    long long idx = (long long)g_diag[33];
    g_diag[40] = dout[idx];
    g_diag[41] = dout[(size_t)100 * D_MODEL + 100];
    g_diag[42] = dout[(size_t)3000 * D_MODEL + 500];
}

// ---------------- RMSNorm ----------------------------------------------------
__global__ void k_rmsnorm(const float* __restrict__ x,
                          const float* __restrict__ w,
                          float* __restrict__ xn) {
    int row = blockIdx.x;
    const float* xr = x + (size_t)row * D_MODEL;
    float s = 0.f;
    for (int i = threadIdx.x; i < D_MODEL; i += 256) {
        float v = xr[i];
        s += v * v;
    }
    __shared__ float red[8];
    for (int o = 16; o > 0; o >>= 1) s += __shfl_xor_sync(~0u, s, o);
    if ((threadIdx.x & 31) == 0) red[threadIdx.x >> 5] = s;
    __syncthreads();
    if (threadIdx.x < 8) {
        s = red[threadIdx.x];
        for (int o = 4; o > 0; o >>= 1) s += __shfl_xor_sync(0xff, s, o);
        if (threadIdx.x == 0) red[0] = s;
    }
    __syncthreads();
    float rinv = rsqrtf(red[0] / (float)D_MODEL + 1e-6f);
    float* o = xn + (size_t)row * D_MODEL;
    for (int i = threadIdx.x; i < D_MODEL; i += 256) o[i] = xr[i] * rinv * w[i];
}

// ---------------- textbook GEMM (GEMM1 only; gold-verified on this shape) --
__global__ void k_gemm1(const float* __restrict__ A,
                        const float* __restrict__ B,
                        float* __restrict__ C,
                        int M, int N, int K) {
    __shared__ float As[32][65];
    __shared__ float Bs[32][65];
    int tid = threadIdx.x;
    int tx = tid & 15;
    int ty = tid >> 4;
    int mBase = blockIdx.y * 64;
    int nBase = blockIdx.x * 64;

    float acc[4][4] = {};

    for (int k0 = 0; k0 < K; k0 += 32) {
        for (int i = tid; i < 64 * 32; i += 256) {
            int m = i >> 5, k = i & 31;
            As[k][m] = A[(size_t)(mBase + m) * K + k0 + k];
        }
        for (int i = tid; i < 32 * 64; i += 256) {
            int k = i >> 6, n = i & 63;
            Bs[k][n] = B[(size_t)(k0 + k) * N + nBase + n];
        }
        __syncthreads();
#pragma unroll 8
        for (int k = 0; k < 32; k++) {
            float a[4], b[4];
#pragma unroll
            for (int i = 0; i < 4; i++) a[i] = As[k][ty * 4 + i];
#pragma unroll
            for (int j = 0; j < 4; j++) b[j] = Bs[k][tx * 4 + j];
#pragma unroll
            for (int i = 0; i < 4; i++)
#pragma unroll
                for (int j = 0; j < 4; j++) acc[i][j] += a[i] * b[j];
        }
        __syncthreads();
    }

#pragma unroll
    for (int i = 0; i < 4; i++) {
        int row = mBase + ty * 4 + i;
#pragma unroll
        for (int j = 0; j < 4; j++) {
            int col = nBase + tx * 4 + j;
            C[(size_t)row * N + col] = acc[i][j];
        }
    }
}

// ---------------- GEMM2: per-output dot product, mirrors gold exactly ------
// out[row, col] = x[row, col] + sum_k yf[row, k] * W_out[k, col]
__global__ void k_gemm2(const float* __restrict__ yf,
                        const float* __restrict__ W,
                        const float* __restrict__ x,
                        float* __restrict__ out) {
    __shared__ float s_a[256];
    int row = blockIdx.y;
    int col = blockIdx.x * 256 + threadIdx.x;
    float acc = 0.f;
    for (int k0 = 0; k0 < D_INNER; k0 += 256) {
        __syncthreads();
        s_a[threadIdx.x] = yf[(size_t)row * D_INNER + k0 + threadIdx.x];
        __syncthreads();
#pragma unroll 8
        for (int k = 0; k < 256; k++)
            acc += s_a[k] * W[(size_t)(k0 + k) * D_MODEL + col];
    }
    out[(size_t)row * D_MODEL + col] =
        acc + x[(size_t)row * D_MODEL + col];
}

// ---------------- causal depthwise conv (D_CONV=4) + SiLU ------------------
__global__ void k_conv(const float* __restrict__ xz,
                       const float* __restrict__ cw,
                       const float* __restrict__ cb,
                       float* __restrict__ xc) {
    int idx = blockIdx.x * blockDim.x + threadIdx.x;
    if (idx >= NTOK * D_INNER) return;
    int c = idx & (D_INNER - 1);
    int m = idx >> 11;
    int t = m & (T_LEN - 1);
    float acc = cb[c];
#pragma unroll
    for (int k = 0; k < 4; k++) {
        int tt = t - 3 + k;
        if (tt >= 0)
            acc += xz[(size_t)(m - 3 + k) * (2 * D_INNER) + c] * cw[c * 4 + k];
    }
    xc[idx] = acc / (1.f + __expf(-acc));
}

// ---------------- small GEMM: ssm = xc @ W_x  (N=33) -----------------------
__global__ void k_xproj(const float* __restrict__ xc,
                        const float* __restrict__ Wx,
                        float* __restrict__ ssm) {
    int idx = blockIdx.x * blockDim.x + threadIdx.x;
    if (idx >= NTOK * NPROJ) return;
    int m = idx / NPROJ;
    int n = idx - m * NPROJ;
    const float* xr = xc + (size_t)m * D_INNER;
    float acc = 0.f;
#pragma unroll 4
    for (int k = 0; k < D_INNER; k++) acc += xr[k] * Wx[k * NPROJ + n];
    ssm[idx] = acc;
}

// ---------------- selective scan + fused gate epilogue ---------------------
__global__ void k_scan(const float* __restrict__ ssm,
                       const float* __restrict__ xc,
                       const float* __restrict__ xz,
                       const float* __restrict__ A_log,
                       const float* __restrict__ w_dt,
                       const float* __restrict__ b_dt,
                       const float* __restrict__ Dp,
                       float* __restrict__ yf) {
    int s = threadIdx.x & 15;
    int c = blockIdx.x * 16 + (threadIdx.x >> 4);
    int b = blockIdx.y;

    float A = -__expf(A_log[c * D_STATE + s]);
    float wdt = w_dt[c], bdt = b_dt[c], dpar = Dp[c];
    float h = 0.f;
    size_t base = (size_t)b * T_LEN;

    for (int t = 0; t < T_LEN; t++) {
        size_t row = base + t;
        const float* sr = ssm + row * NPROJ;
        float dtr = sr[0];
        float Bv  = sr[1 + s];
        float Cv  = sr[1 + D_STATE + s];
        float xcv = xc[row * D_INNER + c];

        float pre = dtr * wdt + bdt;
        float dt = (pre > 20.f) ? pre : log1pf(__expf(pre));

        h = __expf(dt * A) * h + (dt * Bv) * xcv;

        float p = h * Cv;
        p += __shfl_xor_sync(~0u, p, 8);
        p += __shfl_xor_sync(~0u, p, 4);
        p += __shfl_xor_sync(~0u, p, 2);
        p += __shfl_xor_sync(~0u, p, 1);

        if (s == 0) {
            float z = xz[row * (2 * D_INNER) + D_INNER + c];
            float zs = z / (1.f + __expf(-z));
            yf[row * D_INNER + c] = (p + xcv * dpar) * zs;
        }
    }
}

// ---------------- launch ----------------------------------------------------
extern "C" void kernel_launch(void* const* d_in, const int* in_sizes, int n_in,
                              void* d_out, int out_size) {
    const float* x      = (const float*)d_in[0];
    const float* norm_w = (const float*)d_in[1];
    const float* W_in   = (const float*)d_in[2];
    const float* conv_w = (const float*)d_in[3];
    const float* conv_b = (const float*)d_in[4];
    const float* W_x    = (const float*)d_in[5];
    const float* w_dt   = (const float*)d_in[6];
    const float* b_dt   = (const float*)d_in[7];
    const float* A_log  = (const float*)d_in[8];
    const float* D_par  = (const float*)d_in[9];
    const float* W_out  = (const float*)d_in[10];
    float* out = (float*)d_out;

    float *xn, *xz, *xc, *ssm, *yf, *stage;
    double *accp, *diagp;
    int* maxp;
    cudaGetSymbolAddress((void**)&xn,    g_xn);
    cudaGetSymbolAddress((void**)&xz,    g_xz);
    cudaGetSymbolAddress((void**)&xc,    g_xc);
    cudaGetSymbolAddress((void**)&ssm,   g_ssm);
    cudaGetSymbolAddress((void**)&yf,    g_yf);
    cudaGetSymbolAddress((void**)&stage, g_out);
    cudaGetSymbolAddress((void**)&accp,  g_acc);
    cudaGetSymbolAddress((void**)&maxp,  g_max);
    cudaGetSymbolAddress((void**)&diagp, g_diag);

    cudaStreamCaptureStatus c0 = cudaStreamCaptureStatusNone;
    cudaStreamCaptureStatus c1 = cudaStreamCaptureStatusNone;
    cudaStreamCaptureStatus c2 = cudaStreamCaptureStatusNone;
    cudaStreamIsCapturing((cudaStream_t)0, &c0);
    cudaStreamIsCapturing(cudaStreamPerThread, &c1);
    cudaStreamIsCapturing(cudaStreamLegacy, &c2);
    cudaGetLastError();
    bool dbg = (c0 == cudaStreamCaptureStatusNone) &&
               (c1 == cudaStreamCaptureStatusNone) &&
               (c2 == cudaStreamCaptureStatusNone);

    // ---- the pipeline ----
    k_rmsnorm<<<NTOK, 256>>>(x, norm_w, xn);
    k_gemm1<<<dim3(4096 / 64, NTOK / 64), 256>>>(xn, W_in, xz,
                                                 NTOK, 2 * D_INNER, D_MODEL);
    k_conv<<<(NTOK * D_INNER + 255) / 256, 256>>>(xz, conv_w, conv_b, xc);
    k_xproj<<<(NTOK * NPROJ + 255) / 256, 256>>>(xc, W_x, ssm);
    k_scan<<<dim3(D_INNER / 16, B_SZ), 256>>>(ssm, xc, xz, A_log, w_dt, b_dt,
                                              D_par, yf);
    k_gemm2<<<dim3(D_MODEL / 256, NTOK), 256>>>(yf, W_out, x, stage);

    cudaMemcpyAsync(out, stage, (size_t)NTOK * D_MODEL * sizeof(float),
                    cudaMemcpyDeviceToDevice, 0);

    // ---- diagnostics: ONLY when provably not capturing ----
    if (dbg) {
        cudaMemsetAsync(accp, 0, 8 * sizeof(double), 0);
        cudaMemsetAsync(maxp, 0, 8 * sizeof(int), 0);
        cudaMemsetAsync(diagp, 0, 64 * sizeof(double), 0);
        k_stat<<<256, 256>>>(yf,    (long long)NTOK * D_INNER, 4);
        k_stat<<<256, 256>>>(stage, (long long)NTOK * D_MODEL, 5);
        k_argmax<<<1, 256>>>(stage, (long long)NTOK * D_MODEL);
        k_gold<<<1, 32>>>(yf, W_out, x, stage, xn, W_in, xz);
        k_readback<<<1, 32>>>(out);
        double h[8] = {0}, d[64] = {0};
        int hm[8] = {0};
        cudaMemcpyAsync(h, accp, 8 * sizeof(double), cudaMemcpyDeviceToHost, 0);
        cudaMemcpyAsync(hm, maxp, 8 * sizeof(int), cudaMemcpyDeviceToHost, 0);
        cudaMemcpyAsync(d, diagp, 64 * sizeof(double), cudaMemcpyDeviceToHost, 0);
        cudaError_t e = cudaStreamSynchronize(0);

        double nxm = (double)NTOK * D_MODEL;
        double nxi = (double)NTOK * D_INNER;
        double mean_out = h[5] / nxm;

        auto bad = [](double gold, double got) {
            double diff = fabs(gold - got);
            double den = fabs(gold) > 1e-3 ? fabs(gold) : 1e-3;
            return diff / den > 1e-2;
        };
        bool mism_stage = bad(d[0], d[1]) || bad(d[2], d[3]) || bad(d[4], d[5]);
        bool mism_g1    = bad(d[6], d[7]);
        bool mism_dout  = bad(d[1], d[40]) || bad(d[3], d[41]) || bad(d[5], d[42]);

        for (int f = 0; f < 2; f++) {
            FILE* o = f ? stdout : stderr;
            fprintf(o,
                "DIAG err=%s mean_out=%.4g mism_stage=%d mism_g1=%d mism_dout=%d\n"
                "DIAG ptrs x=%p W_out=%p d_out=%p stage=%p\n"
                "DIAG mean|yf|=%.4g max|yf|=%.4g mean|stage|=%.4g max|stage|=%.4g\n"
                "DIAG argmax(row=%.0f,col=%.0f): gold=%.6g stage=%.6g dout=%.6g\n"
                "DIAG (100,100):  gold=%.6g stage=%.6g dout=%.6g\n"
                "DIAG (3000,500): gold=%.6g stage=%.6g dout=%.6g\n"
                "DIAG gemm1 xz[1000,3000]: gold=%.6g got=%.6g\n",
                cudaGetErrorString(e), mean_out, (int)mism_stage, (int)mism_g1,
                (int)mism_dout,
                (const void*)x, (const void*)W_out, (void*)out, (void*)stage,
                h[4] / nxi, host_bits_to_float(hm[4]),
                mean_out, host_bits_to_float(hm[5]),
                d[34], d[35], d[0], d[1], d[40],
                d[2], d[3], d[41],
                d[4], d[5], d[42],
                d[6], d[7]);
            fflush(o);
        }
        if (mean_out > 3.0 || mism_stage || mism_g1 || mism_dout) abort();
    }
}

// round 17
// speedup vs baseline: 1.4472x; 1.4472x over previous
#include <cuda_runtime.h>
#include <math.h>

#define T_LEN   2048
#define B_SZ    2
#define D_MODEL 1024
#define D_INNER 2048
#define D_STATE 16
#define NTOK    (B_SZ * T_LEN)   // 4096
#define NPROJ   33               // 1 + 2*D_STATE

// ---------------- scratch (device globals; no allocation allowed) ----------
__device__ float g_xn[(size_t)NTOK * D_MODEL];
__device__ float g_xz[(size_t)NTOK * 2 * D_INNER];
__device__ float g_xc[(size_t)NTOK * D_INNER];
__device__ float g_ssm[(size_t)NTOK * NPROJ];
__device__ float g_yf[(size_t)NTOK * D_INNER];

// ---------------- RMSNorm ----------------------------------------------------
__global__ void k_rmsnorm(const float* __restrict__ x,
                          const float* __restrict__ w,
                          float* __restrict__ xn) {
    int row = blockIdx.x;
    const float* xr = x + (size_t)row * D_MODEL;
    float s = 0.f;
    for (int i = threadIdx.x; i < D_MODEL; i += 256) {
        float v = xr[i];
        s += v * v;
    }
    __shared__ float red[8];
    for (int o = 16; o > 0; o >>= 1) s += __shfl_xor_sync(~0u, s, o);
    if ((threadIdx.x & 31) == 0) red[threadIdx.x >> 5] = s;
    __syncthreads();
    if (threadIdx.x < 8) {
        s = red[threadIdx.x];
        for (int o = 4; o > 0; o >>= 1) s += __shfl_xor_sync(0xff, s, o);
        if (threadIdx.x == 0) red[0] = s;
    }
    __syncthreads();
    float rinv = rsqrtf(red[0] / (float)D_MODEL + 1e-6f);
    float* o = xn + (size_t)row * D_MODEL;
    for (int i = threadIdx.x; i < D_MODEL; i += 256) o[i] = xr[i] * rinv * w[i];
}

// ---------------- fast fp32 SGEMM: 128x128 tile, 8x8 per thread ------------
// C[M,N] = A[M,K] @ B[K,N]  (+ R[M,N] if RESID)   [gold-verified R13]
template <bool RESID>
__global__ void k_sgemm(const float* __restrict__ A,
                        const float* __restrict__ B,
                        float* __restrict__ C,
                        const float* __restrict__ R,
                        int M, int N, int K) {
    __shared__ float As[8][128];
    __shared__ float Bs[8][128];
    int tid = threadIdx.x;            // 256 threads
    int tx = tid & 15;
    int ty = tid >> 4;

    const float* Ab = A + (size_t)(blockIdx.y * 128) * K;
    const float* Bb = B + blockIdx.x * 128;

    int aRow = tid >> 1;              // 128 rows, 2 threads/row
    int aCol = (tid & 1) * 4;
    int bRow = tid >> 5;              // 8 rows, 32 threads/row
    int bCol = (tid & 31) * 4;

    float acc[8][8] = {};

    for (int k0 = 0; k0 < K; k0 += 8) {
        float4 a4 = *(const float4*)(Ab + (size_t)aRow * K + k0 + aCol);
        As[aCol + 0][aRow] = a4.x;
        As[aCol + 1][aRow] = a4.y;
        As[aCol + 2][aRow] = a4.z;
        As[aCol + 3][aRow] = a4.w;
        *(float4*)&Bs[bRow][bCol] =
            *(const float4*)(Bb + (size_t)(k0 + bRow) * N + bCol);
        __syncthreads();
#pragma unroll
        for (int kk = 0; kk < 8; kk++) {
            float ar[8], br[8];
            *(float4*)(ar)     = *(float4*)&As[kk][ty * 8];
            *(float4*)(ar + 4) = *(float4*)&As[kk][ty * 8 + 4];
            *(float4*)(br)     = *(float4*)&Bs[kk][tx * 8];
            *(float4*)(br + 4) = *(float4*)&Bs[kk][tx * 8 + 4];
#pragma unroll
            for (int i = 0; i < 8; i++)
#pragma unroll
                for (int j = 0; j < 8; j++) acc[i][j] += ar[i] * br[j];
        }
        __syncthreads();
    }

#pragma unroll
    for (int i = 0; i < 8; i++) {
        int row = blockIdx.y * 128 + ty * 8 + i;
        float* cp = C + (size_t)row * N + blockIdx.x * 128 + tx * 8;
        if (RESID) {
            const float* rp = R + (size_t)row * N + blockIdx.x * 128 + tx * 8;
#pragma unroll
            for (int j = 0; j < 8; j++) cp[j] = acc[i][j] + rp[j];
        } else {
#pragma unroll
            for (int j = 0; j < 8; j++) cp[j] = acc[i][j];
        }
    }
}

// ---------------- causal depthwise conv (D_CONV=4) + SiLU ------------------
__global__ void k_conv(const float* __restrict__ xz,
                       const float* __restrict__ cw,
                       const float* __restrict__ cb,
                       float* __restrict__ xc) {
    int idx = blockIdx.x * blockDim.x + threadIdx.x;
    if (idx >= NTOK * D_INNER) return;
    int c = idx & (D_INNER - 1);
    int m = idx >> 11;
    int t = m & (T_LEN - 1);
    float acc = cb[c];
#pragma unroll
    for (int k = 0; k < 4; k++) {
        int tt = t - 3 + k;
        if (tt >= 0)
            acc += xz[(size_t)(m - 3 + k) * (2 * D_INNER) + c] * cw[c * 4 + k];
    }
    xc[idx] = acc / (1.f + __expf(-acc));
}

// ---------------- small GEMM: ssm = xc @ W_x  (N=33) -----------------------
__global__ void k_xproj(const float* __restrict__ xc,
                        const float* __restrict__ Wx,
                        float* __restrict__ ssm) {
    int idx = blockIdx.x * blockDim.x + threadIdx.x;
    if (idx >= NTOK * NPROJ) return;
    int m = idx / NPROJ;
    int n = idx - m * NPROJ;
    const float* xr = xc + (size_t)m * D_INNER;
    float acc = 0.f;
#pragma unroll 4
    for (int k = 0; k < D_INNER; k++) acc += xr[k] * Wx[k * NPROJ + n];
    ssm[idx] = acc;
}

// ---------------- selective scan + fused gate epilogue ---------------------
__global__ void k_scan(const float* __restrict__ ssm,
                       const float* __restrict__ xc,
                       const float* __restrict__ xz,
                       const float* __restrict__ A_log,
                       const float* __restrict__ w_dt,
                       const float* __restrict__ b_dt,
                       const float* __restrict__ Dp,
                       float* __restrict__ yf) {
    int s = threadIdx.x & 15;
    int c = blockIdx.x * 16 + (threadIdx.x >> 4);
    int b = blockIdx.y;

    float A = -__expf(A_log[c * D_STATE + s]);
    float wdt = w_dt[c], bdt = b_dt[c], dpar = Dp[c];
    float h = 0.f;
    size_t base = (size_t)b * T_LEN;

    for (int t = 0; t < T_LEN; t++) {
        size_t row = base + t;
        const float* sr = ssm + row * NPROJ;
        float dtr = sr[0];
        float Bv  = sr[1 + s];
        float Cv  = sr[1 + D_STATE + s];
        float xcv = xc[row * D_INNER + c];

        float pre = dtr * wdt + bdt;
        float dt = (pre > 20.f) ? pre : log1pf(__expf(pre));

        h = __expf(dt * A) * h + (dt * Bv) * xcv;

        float p = h * Cv;
        p += __shfl_xor_sync(~0u, p, 8);
        p += __shfl_xor_sync(~0u, p, 4);
        p += __shfl_xor_sync(~0u, p, 2);
        p += __shfl_xor_sync(~0u, p, 1);

        if (s == 0) {
            float z = xz[row * (2 * D_INNER) + D_INNER + c];
            float zs = z / (1.f + __expf(-z));
            yf[row * D_INNER + c] = (p + xcv * dpar) * zs;
        }
    }
}

// ---------------- launch ----------------------------------------------------
extern "C" void kernel_launch(void* const* d_in, const int* in_sizes, int n_in,
                              void* d_out, int out_size) {
    const float* x      = (const float*)d_in[0];
    const float* norm_w = (const float*)d_in[1];
    const float* W_in   = (const float*)d_in[2];
    const float* conv_w = (const float*)d_in[3];
    const float* conv_b = (const float*)d_in[4];
    const float* W_x    = (const float*)d_in[5];
    const float* w_dt   = (const float*)d_in[6];
    const float* b_dt   = (const float*)d_in[7];
    const float* A_log  = (const float*)d_in[8];
    const float* D_par  = (const float*)d_in[9];
    const float* W_out  = (const float*)d_in[10];
    float* out = (float*)d_out;

    float *xn, *xz, *xc, *ssm, *yf;
    cudaGetSymbolAddress((void**)&xn,  g_xn);
    cudaGetSymbolAddress((void**)&xz,  g_xz);
    cudaGetSymbolAddress((void**)&xc,  g_xc);
    cudaGetSymbolAddress((void**)&ssm, g_ssm);
    cudaGetSymbolAddress((void**)&yf,  g_yf);

    // 1. RMSNorm
    k_rmsnorm<<<NTOK, 256>>>(x, norm_w, xn);

    // 2. xz = xn @ W_in   [M=4096, N=4096, K=1024]
    k_sgemm<false><<<dim3(4096 / 128, NTOK / 128), 256>>>(
        xn, W_in, xz, nullptr, NTOK, 2 * D_INNER, D_MODEL);

    // 3. causal depthwise conv + SiLU -> xc
    k_conv<<<(NTOK * D_INNER + 255) / 256, 256>>>(xz, conv_w, conv_b, xc);

    // 4. ssm = xc @ W_x   [4096 x 33 x 2048]
    k_xproj<<<(NTOK * NPROJ + 255) / 256, 256>>>(xc, W_x, ssm);

    // 5. selective scan + D-skip + silu(z) gate -> yf
    k_scan<<<dim3(D_INNER / 16, B_SZ), 256>>>(ssm, xc, xz, A_log, w_dt, b_dt,
                                              D_par, yf);

    // 6. out = yf @ W_out + x   [M=4096, N=1024, K=2048]  <-- K FIXED
    k_sgemm<true><<<dim3(D_MODEL / 128, NTOK / 128), 256>>>(
        yf, W_out, out, x, NTOK, D_MODEL, D_INNER);
}